// round 1
// baseline (speedup 1.0000x reference)
#include <cuda_runtime.h>

// Problem constants
#define PB 32
#define PS 4096
#define PF 64
#define PF4 16                         // F in float4 units
#define T1 2048
#define T2 1024
#define T3 512
#define T4 256
#define T5 128
#define BSF (32LL * 4096LL * 64LL)     // 8,388,608 elements per output region

// Analysis filters: H = reversed db4 dec filters (cross-correlation form)
__constant__ float c_H0[8] = {
     0.23037781330885523f,  0.7148465705525415f,   0.6308807679295904f,
    -0.02798376941698385f, -0.18703481171888114f,  0.030841381835986965f,
     0.032883011666982945f, -0.010597401784997278f };
__constant__ float c_H1[8] = {
    -0.010597401784997278f, -0.032883011666982945f, 0.030841381835986965f,
     0.18703481171888114f,  -0.02798376941698385f, -0.6308807679295904f,
     0.7148465705525415f,   -0.23037781330885523f };

// Static scratch (allocation is forbidden; __device__ globals are the sanctioned path)
__device__ float g_lo1[PB * T1 * PF];
__device__ float g_hi1[PB * T1 * PF];
__device__ float g_lo2[PB * T2 * PF];
__device__ float g_hi2[PB * T2 * PF];
__device__ float g_lo3[PB * T3 * PF];
__device__ float g_hi3[PB * T3 * PF];
__device__ float g_lo4[PB * T4 * PF];
__device__ float g_hi4[PB * T4 * PF];
__device__ float g_lo5[PB * T5 * PF];
__device__ float g_hi5[PB * T5 * PF];

__device__ __forceinline__ float* lo_ptr(int level) {
    switch (level) {
        case 1: return g_lo1;
        case 2: return g_lo2;
        case 3: return g_lo3;
        case 4: return g_lo4;
        default: return g_lo5;
    }
}
__device__ __forceinline__ float* hi_ptr(int level) {
    switch (level) {
        case 1: return g_hi1;
        case 2: return g_hi2;
        case 3: return g_hi3;
        case 4: return g_hi4;
        default: return g_hi5;
    }
}

// One analysis level: in (B, T_IN, F) -> lo,hi (B, T_OUT, F), T_OUT = T_IN/2.
// out[n] = sum_k H[k] * in[2n + k - 3], zero outside [0, T_IN).
// Threads: f4 = tid & 15 (float4 along F), 16 n-rows per block.
template <int LEVEL>
__global__ void afb_kernel(const float4* __restrict__ x) {
    constexpr int T_IN  = PS >> (LEVEL - 1);
    constexpr int T_OUT = PS >> LEVEL;

    const int f4 = threadIdx.x & 15;
    const int n  = (blockIdx.x << 4) + (threadIdx.x >> 4);
    const int b  = blockIdx.y;

    const float4* in = (LEVEL == 1) ? x : (const float4*)lo_ptr(LEVEL - 1);
    float4* lo = (float4*)lo_ptr(LEVEL);
    float4* hi = (float4*)hi_ptr(LEVEL);

    const float4* inb = in + (size_t)b * T_IN * PF4 + f4;

    float4 al = make_float4(0.f, 0.f, 0.f, 0.f);
    float4 ah = make_float4(0.f, 0.f, 0.f, 0.f);
    const int base = 2 * n - 3;
#pragma unroll
    for (int k = 0; k < 8; ++k) {
        const int idx = base + k;
        if (idx >= 0 && idx < T_IN) {
            const float4 v = __ldg(inb + (size_t)idx * PF4);
            const float h0 = c_H0[k], h1 = c_H1[k];
            al.x = fmaf(h0, v.x, al.x); al.y = fmaf(h0, v.y, al.y);
            al.z = fmaf(h0, v.z, al.z); al.w = fmaf(h0, v.w, al.w);
            ah.x = fmaf(h1, v.x, ah.x); ah.y = fmaf(h1, v.y, ah.y);
            ah.z = fmaf(h1, v.z, ah.z); ah.w = fmaf(h1, v.w, ah.w);
        }
    }
    const size_t o = ((size_t)b * T_OUT + n) * PF4 + f4;
    lo[o] = al;
    hi[o] = ah;
}

__device__ __forceinline__ float approx_fetch(int L, int b, int s, int f) {
    switch (L) {
        case 2: return (s < T2) ? __ldg(g_lo2 + ((size_t)b * T2 + s) * PF + f) : 0.f;
        case 3: return (s < T3) ? __ldg(g_lo3 + ((size_t)b * T3 + s) * PF + f) : 0.f;
        case 4: return (s < T4) ? __ldg(g_lo4 + ((size_t)b * T4 + s) * PF + f) : 0.f;
        default: return (s < T5) ? __ldg(g_lo5 + ((size_t)b * T5 + s) * PF + f) : 0.f;
    }
}

// Assemble the full output: every element written exactly once, float4 coalesced.
// Regions (each BSF floats): [0]=approx [1..5]=details [6]=high_freq [7]=low_freq
__global__ void assemble_kernel(const float* __restrict__ scores, float4* __restrict__ out) {
    const int f4 = threadIdx.x & 15;
    const int s  = (blockIdx.x << 4) + (threadIdx.x >> 4);
    const int b  = blockIdx.y;

    // per-component decomposition level: clip(2 + rne(score*3), 2, 5)
    const float4 sc = __ldg((const float4*)scores + f4);
    const int L0 = min(5, max(2, 2 + __float2int_rn(sc.x * 3.0f)));
    const int L1 = min(5, max(2, 2 + __float2int_rn(sc.y * 3.0f)));
    const int L2 = min(5, max(2, 2 + __float2int_rn(sc.z * 3.0f)));
    const int L3 = min(5, max(2, 2 + __float2int_rn(sc.w * 3.0f)));

    const float4 zero = make_float4(0.f, 0.f, 0.f, 0.f);

    float4 d0 = (s < T1) ? __ldg((const float4*)g_hi1 + ((size_t)b * T1 + s) * PF4 + f4) : zero;
    float4 d1 = (s < T2) ? __ldg((const float4*)g_hi2 + ((size_t)b * T2 + s) * PF4 + f4) : zero;
    float4 d2 = (s < T3) ? __ldg((const float4*)g_hi3 + ((size_t)b * T3 + s) * PF4 + f4) : zero;
    float4 d3 = (s < T4) ? __ldg((const float4*)g_hi4 + ((size_t)b * T4 + s) * PF4 + f4) : zero;
    float4 d4 = (s < T5) ? __ldg((const float4*)g_hi5 + ((size_t)b * T5 + s) * PF4 + f4) : zero;

    // detail i kept iff i < level (i=0,1 always kept since level >= 2)
    d2.x = (L0 > 2) ? d2.x : 0.f;  d2.y = (L1 > 2) ? d2.y : 0.f;
    d2.z = (L2 > 2) ? d2.z : 0.f;  d2.w = (L3 > 2) ? d2.w : 0.f;
    d3.x = (L0 > 3) ? d3.x : 0.f;  d3.y = (L1 > 3) ? d3.y : 0.f;
    d3.z = (L2 > 3) ? d3.z : 0.f;  d3.w = (L3 > 3) ? d3.w : 0.f;
    d4.x = (L0 > 4) ? d4.x : 0.f;  d4.y = (L1 > 4) ? d4.y : 0.f;
    d4.z = (L2 > 4) ? d4.z : 0.f;  d4.w = (L3 > 4) ? d4.w : 0.f;

    float4 a;
    const int f = f4 * 4;
    a.x = approx_fetch(L0, b, s, f + 0);
    a.y = approx_fetch(L1, b, s, f + 1);
    a.z = approx_fetch(L2, b, s, f + 2);
    a.w = approx_fetch(L3, b, s, f + 3);

    float4 hf;
    hf.x = d0.x + d1.x + d2.x + d3.x + d4.x;
    hf.y = d0.y + d1.y + d2.y + d3.y + d4.y;
    hf.z = d0.z + d1.z + d2.z + d3.z + d4.z;
    hf.w = d0.w + d1.w + d2.w + d3.w + d4.w;

    const size_t idx = ((size_t)b * PS + s) * PF4 + f4;
    const size_t R = (size_t)(BSF / 4);   // region stride in float4
    out[idx]         = a;
    out[R + idx]     = d0;
    out[2 * R + idx] = d1;
    out[3 * R + idx] = d2;
    out[4 * R + idx] = d3;
    out[5 * R + idx] = d4;
    out[6 * R + idx] = hf;
    out[7 * R + idx] = a;   // low_freq == approx
}

extern "C" void kernel_launch(void* const* d_in, const int* in_sizes, int n_in,
                              void* d_out, int out_size) {
    const float4* x      = (const float4*)d_in[0];   // (32, 4096, 64) f32
    const float*  scores = (const float*)d_in[1];    // (64,) f32
    float4* out = (float4*)d_out;

    const dim3 blk(256);
    afb_kernel<1><<<dim3(T1 / 16, PB), blk>>>(x);
    afb_kernel<2><<<dim3(T2 / 16, PB), blk>>>(x);
    afb_kernel<3><<<dim3(T3 / 16, PB), blk>>>(x);
    afb_kernel<4><<<dim3(T4 / 16, PB), blk>>>(x);
    afb_kernel<5><<<dim3(T5 / 16, PB), blk>>>(x);
    assemble_kernel<<<dim3(PS / 16, PB), blk>>>(scores, out);
}

// round 2
// speedup vs baseline: 1.1056x; 1.1056x over previous
#include <cuda_runtime.h>

// Problem constants
#define PB 32
#define PS 4096
#define PF 64
#define PF4 16                         // F in float4 units
#define T1 2048
#define T2 1024
#define T3 512
#define T4 256
#define T5 128
#define BSF (32LL * 4096LL * 64LL)     // elements per output region

// Analysis filters: H = reversed db4 dec filters (cross-correlation form)
__constant__ float c_H0[8] = {
     0.23037781330885523f,  0.7148465705525415f,   0.6308807679295904f,
    -0.02798376941698385f, -0.18703481171888114f,  0.030841381835986965f,
     0.032883011666982945f, -0.010597401784997278f };
__constant__ float c_H1[8] = {
    -0.010597401784997278f, -0.032883011666982945f, 0.030841381835986965f,
     0.18703481171888114f,  -0.02798376941698385f, -0.6308807679295904f,
     0.7148465705525415f,   -0.23037781330885523f };

// Static scratch.
// hi1 kept in (B,T,F) layout (written coalesced by level1, read coalesced by assemble).
// Everything else in column-major (B,F4,T) layout: element (b,f4,t) is a float4 of
// 4 adjacent features; contiguous in t. Sector-efficient for the assemble read pattern.
__device__ float4 g_hi1 [PB * T1 * PF4];   // (B,T1,F)
__device__ float4 g_lo1t[PB * PF4 * T1];   // (B,F4,T1)
__device__ float4 g_lo2t[PB * PF4 * T2];
__device__ float4 g_hi2t[PB * PF4 * T2];
__device__ float4 g_lo3t[PB * PF4 * T3];
__device__ float4 g_hi3t[PB * PF4 * T3];
__device__ float4 g_lo4t[PB * PF4 * T4];
__device__ float4 g_hi4t[PB * PF4 * T4];
__device__ float4 g_lo5t[PB * PF4 * T5];
__device__ float4 g_hi5t[PB * PF4 * T5];

// ---------------------------------------------------------------------------
// Kernel A: level 1.  (B,S,F) input -> hi1 (B,T1,F) + lo1 (B,F4,T1 via transpose)
// ---------------------------------------------------------------------------
__global__ void level1_kernel(const float4* __restrict__ x) {
    __shared__ float4 s_lo[16][17];    // padded to kill bank conflicts

    const int f4 = threadIdx.x & 15;
    const int nl = threadIdx.x >> 4;
    const int n  = (blockIdx.x << 4) + nl;
    const int b  = blockIdx.y;

    const float4* inb = x + (size_t)b * PS * PF4 + f4;

    float4 al = make_float4(0.f, 0.f, 0.f, 0.f);
    float4 ah = make_float4(0.f, 0.f, 0.f, 0.f);
    const int base = 2 * n - 3;
#pragma unroll
    for (int k = 0; k < 8; ++k) {
        const int idx = base + k;
        if (idx >= 0 && idx < PS) {
            const float4 v = __ldg(inb + (size_t)idx * PF4);
            const float h0 = c_H0[k], h1 = c_H1[k];
            al.x = fmaf(h0, v.x, al.x); al.y = fmaf(h0, v.y, al.y);
            al.z = fmaf(h0, v.z, al.z); al.w = fmaf(h0, v.w, al.w);
            ah.x = fmaf(h1, v.x, ah.x); ah.y = fmaf(h1, v.y, ah.y);
            ah.z = fmaf(h1, v.z, ah.z); ah.w = fmaf(h1, v.w, ah.w);
        }
    }
    // hi1: (B,T1,F) coalesced direct
    g_hi1[((size_t)b * T1 + n) * PF4 + f4] = ah;

    // lo1: transpose through smem -> (B,F4,T1) coalesced
    s_lo[nl][f4] = al;
    __syncthreads();
    const int f4o = threadIdx.x >> 4;
    const int no  = threadIdx.x & 15;
    g_lo1t[((size_t)b * PF4 + f4o) * T1 + (blockIdx.x << 4) + no] = s_lo[no][f4o];
}

// ---------------------------------------------------------------------------
// Kernel B: fused levels 2..5, one block per (b,f4) column, cascade in smem.
// Buffers hold signal with 3 left + 3 right zero guard cells:
//   buf[3+j] = signal[j];  read signal[2n-3+k] == buf[2n+k], max idx = T_in+5.
// ---------------------------------------------------------------------------
#define CASC_SMEM ((2054 + 1030) * (int)sizeof(float4))

__global__ void cascade_kernel() {
    extern __shared__ float4 sm[];
    float4* A = sm;            // 2054: holds lo1 (T=2048), later lo3 (T=512)
    float4* Bb = sm + 2054;    // 1030: holds lo2 (T=1024), later lo4 (T=256)

    const int col = blockIdx.x;            // b*16 + f4
    const int tid = threadIdx.x;           // 256 threads

    // zero guard cells
    if (tid < 3) {
        A[tid]  = make_float4(0.f, 0.f, 0.f, 0.f);
        A[3 + T1 + tid] = make_float4(0.f, 0.f, 0.f, 0.f);
        Bb[tid] = make_float4(0.f, 0.f, 0.f, 0.f);
        Bb[3 + T2 + tid] = make_float4(0.f, 0.f, 0.f, 0.f);
    }
    // load lo1 column (32KB, coalesced)
    const float4* src = g_lo1t + (size_t)col * T1;
#pragma unroll
    for (int i = tid; i < T1; i += 256) A[3 + i] = __ldg(src + i);
    __syncthreads();

#define AFB_TAPS(BUF, N, LO, HI)                                               \
    {                                                                          \
        LO = make_float4(0.f, 0.f, 0.f, 0.f);                                  \
        HI = make_float4(0.f, 0.f, 0.f, 0.f);                                  \
        _Pragma("unroll")                                                      \
        for (int k = 0; k < 8; ++k) {                                          \
            const float4 v = BUF[2 * (N) + k];                                 \
            const float h0 = c_H0[k], h1 = c_H1[k];                            \
            LO.x = fmaf(h0, v.x, LO.x); LO.y = fmaf(h0, v.y, LO.y);            \
            LO.z = fmaf(h0, v.z, LO.z); LO.w = fmaf(h0, v.w, LO.w);            \
            HI.x = fmaf(h1, v.x, HI.x); HI.y = fmaf(h1, v.y, HI.y);            \
            HI.z = fmaf(h1, v.z, HI.z); HI.w = fmaf(h1, v.w, HI.w);            \
        }                                                                      \
    }

    // level 2: A(T1) -> Bb(T2) + globals
    float4* lo2g = g_lo2t + (size_t)col * T2;
    float4* hi2g = g_hi2t + (size_t)col * T2;
#pragma unroll
    for (int n = tid; n < T2; n += 256) {
        float4 lo, hi; AFB_TAPS(A, n, lo, hi);
        Bb[3 + n] = lo; lo2g[n] = lo; hi2g[n] = hi;
    }
    __syncthreads();

    // level 3: Bb(T2) -> A(T3) + globals   (A no longer needed; re-init guards)
    if (tid < 3) { A[tid] = make_float4(0.f,0.f,0.f,0.f); A[3 + T3 + tid] = make_float4(0.f,0.f,0.f,0.f); }
    __syncthreads();
    float4* lo3g = g_lo3t + (size_t)col * T3;
    float4* hi3g = g_hi3t + (size_t)col * T3;
#pragma unroll
    for (int n = tid; n < T3; n += 256) {
        float4 lo, hi; AFB_TAPS(Bb, n, lo, hi);
        A[3 + n] = lo; lo3g[n] = lo; hi3g[n] = hi;
    }
    __syncthreads();

    // level 4: A(T3) -> Bb(T4) + globals
    if (tid < 3) { Bb[tid] = make_float4(0.f,0.f,0.f,0.f); Bb[3 + T4 + tid] = make_float4(0.f,0.f,0.f,0.f); }
    __syncthreads();
    float4* lo4g = g_lo4t + (size_t)col * T4;
    float4* hi4g = g_hi4t + (size_t)col * T4;
    if (tid < T4) {
        float4 lo, hi; AFB_TAPS(A, tid, lo, hi);
        Bb[3 + tid] = lo; lo4g[tid] = lo; hi4g[tid] = hi;
    }
    __syncthreads();

    // level 5: Bb(T4) -> globals only
    float4* lo5g = g_lo5t + (size_t)col * T5;
    float4* hi5g = g_hi5t + (size_t)col * T5;
    if (tid < T5) {
        float4 lo, hi; AFB_TAPS(Bb, tid, lo, hi);
        lo5g[tid] = lo; hi5g[tid] = hi;
    }
#undef AFB_TAPS
}

// ---------------------------------------------------------------------------
// Kernel C: assemble.  One coalesced float4 write per output element, streaming.
// Regions: [0]=approx [1..5]=details [6]=high_freq [7]=low_freq
// ---------------------------------------------------------------------------
__device__ __forceinline__ float approx_fetch(int L, int bf, int s, int c) {
    switch (L) {
        case 2: return (s < T2) ? __ldg((const float*)(g_lo2t + (size_t)bf * T2 + s) + c) : 0.f;
        case 3: return (s < T3) ? __ldg((const float*)(g_lo3t + (size_t)bf * T3 + s) + c) : 0.f;
        case 4: return (s < T4) ? __ldg((const float*)(g_lo4t + (size_t)bf * T4 + s) + c) : 0.f;
        default: return (s < T5) ? __ldg((const float*)(g_lo5t + (size_t)bf * T5 + s) + c) : 0.f;
    }
}

__global__ void assemble_kernel(const float* __restrict__ scores, float4* __restrict__ out) {
    const int f4 = threadIdx.x & 15;
    const int s  = (blockIdx.x << 4) + (threadIdx.x >> 4);
    const int b  = blockIdx.y;
    const int bf = b * PF4 + f4;

    const float4 sc = __ldg((const float4*)scores + f4);
    const int L0 = min(5, max(2, 2 + __float2int_rn(sc.x * 3.0f)));
    const int L1 = min(5, max(2, 2 + __float2int_rn(sc.y * 3.0f)));
    const int L2 = min(5, max(2, 2 + __float2int_rn(sc.z * 3.0f)));
    const int L3 = min(5, max(2, 2 + __float2int_rn(sc.w * 3.0f)));

    const float4 zero = make_float4(0.f, 0.f, 0.f, 0.f);

    float4 d0 = (s < T1) ? __ldg(g_hi1 + ((size_t)b * T1 + s) * PF4 + f4) : zero;
    float4 d1 = (s < T2) ? __ldg(g_hi2t + (size_t)bf * T2 + s) : zero;
    float4 d2 = (s < T3) ? __ldg(g_hi3t + (size_t)bf * T3 + s) : zero;
    float4 d3 = (s < T4) ? __ldg(g_hi4t + (size_t)bf * T4 + s) : zero;
    float4 d4 = (s < T5) ? __ldg(g_hi5t + (size_t)bf * T5 + s) : zero;

    // detail i kept iff i < level (i=0,1 always kept since level >= 2)
    d2.x = (L0 > 2) ? d2.x : 0.f;  d2.y = (L1 > 2) ? d2.y : 0.f;
    d2.z = (L2 > 2) ? d2.z : 0.f;  d2.w = (L3 > 2) ? d2.w : 0.f;
    d3.x = (L0 > 3) ? d3.x : 0.f;  d3.y = (L1 > 3) ? d3.y : 0.f;
    d3.z = (L2 > 3) ? d3.z : 0.f;  d3.w = (L3 > 3) ? d3.w : 0.f;
    d4.x = (L0 > 4) ? d4.x : 0.f;  d4.y = (L1 > 4) ? d4.y : 0.f;
    d4.z = (L2 > 4) ? d4.z : 0.f;  d4.w = (L3 > 4) ? d4.w : 0.f;

    float4 a;
    a.x = approx_fetch(L0, bf, s, 0);
    a.y = approx_fetch(L1, bf, s, 1);
    a.z = approx_fetch(L2, bf, s, 2);
    a.w = approx_fetch(L3, bf, s, 3);

    float4 hf;
    hf.x = d0.x + d1.x + d2.x + d3.x + d4.x;
    hf.y = d0.y + d1.y + d2.y + d3.y + d4.y;
    hf.z = d0.z + d1.z + d2.z + d3.z + d4.z;
    hf.w = d0.w + d1.w + d2.w + d3.w + d4.w;

    const size_t idx = ((size_t)b * PS + s) * PF4 + f4;
    const size_t R = (size_t)(BSF / 4);   // region stride in float4
    __stcs(out + idx,         a);
    __stcs(out + R + idx,     d0);
    __stcs(out + 2 * R + idx, d1);
    __stcs(out + 3 * R + idx, d2);
    __stcs(out + 4 * R + idx, d3);
    __stcs(out + 5 * R + idx, d4);
    __stcs(out + 6 * R + idx, hf);
    __stcs(out + 7 * R + idx, a);   // low_freq == approx
}

extern "C" void kernel_launch(void* const* d_in, const int* in_sizes, int n_in,
                              void* d_out, int out_size) {
    const float4* x      = (const float4*)d_in[0];   // (32, 4096, 64) f32
    const float*  scores = (const float*)d_in[1];    // (64,) f32
    float4* out = (float4*)d_out;

    cudaFuncSetAttribute(cascade_kernel,
                         cudaFuncAttributeMaxDynamicSharedMemorySize, CASC_SMEM);

    const dim3 blk(256);
    level1_kernel <<<dim3(T1 / 16, PB), blk>>>(x);
    cascade_kernel<<<dim3(PB * PF4), blk, CASC_SMEM>>>();
    assemble_kernel<<<dim3(PS / 16, PB), blk>>>(scores, out);
}

// round 7
// speedup vs baseline: 1.1426x; 1.0334x over previous
#include <cuda_runtime.h>

// Problem constants
#define PB 32
#define PS 4096
#define PF 64
#define PF4 16                         // F in float4 units
#define T1 2048
#define T2 1024
#define T3 512
#define T4 256
#define T5 128
#define BSF (32LL * 4096LL * 64LL)     // elements per output region

// Analysis filters: H = reversed db4 dec filters (cross-correlation form)
__constant__ float c_H0[8] = {
     0.23037781330885523f,  0.7148465705525415f,   0.6308807679295904f,
    -0.02798376941698385f, -0.18703481171888114f,  0.030841381835986965f,
     0.032883011666982945f, -0.010597401784997278f };
__constant__ float c_H1[8] = {
    -0.010597401784997278f, -0.032883011666982945f, 0.030841381835986965f,
     0.18703481171888114f,  -0.02798376941698385f, -0.6308807679295904f,
     0.7148465705525415f,   -0.23037781330885523f };

// Static scratch, column-major (B,F4,T): element (b,f4,t) is a float4 of 4
// adjacent features; contiguous in t.  (hi1 goes straight to the output now.)
__device__ float4 g_lo1t[PB * PF4 * T1];   // (B,F4,T1)
__device__ float4 g_lo2t[PB * PF4 * T2];
__device__ float4 g_hi2t[PB * PF4 * T2];
__device__ float4 g_lo3t[PB * PF4 * T3];
__device__ float4 g_hi3t[PB * PF4 * T3];
__device__ float4 g_lo4t[PB * PF4 * T4];
__device__ float4 g_hi4t[PB * PF4 * T4];
__device__ float4 g_lo5t[PB * PF4 * T5];
__device__ float4 g_hi5t[PB * PF4 * T5];

// ---------------------------------------------------------------------------
// Kernel A: level 1 with register sliding window (R=4 outputs per thread).
// (B,S,F) input -> hi1 DIRECTLY into out region 1 (B,S,F coalesced)
//                + lo1 into (B,F4,T1) scratch via smem transpose.
// ---------------------------------------------------------------------------
__global__ void __launch_bounds__(256) level1_kernel(const float4* __restrict__ x,
                                                     float4* __restrict__ out) {
    __shared__ float4 s_lo[64][17];    // padded: transpose tile, conflict-free

    const int f4   = threadIdx.x & 15;
    const int tq   = threadIdx.x >> 4;       // 0..15
    const int b    = blockIdx.y;
    const int nblk = blockIdx.x << 6;        // 64 outputs per block
    const int n0   = nblk + (tq << 2);       // this thread's first output

    const float4* inb = x + (size_t)b * PS * PF4 + f4;
    const float4 zero = make_float4(0.f, 0.f, 0.f, 0.f);

    // Window of input rows 2n0-3 .. 2n0+10 (14 rows for 4 outputs)
    const int base = 2 * n0 - 3;
    float4 v[14];
#pragma unroll
    for (int i = 0; i < 14; ++i) {
        const int idx = base + i;
        v[i] = (idx >= 0 && idx < PS) ? __ldg(inb + (size_t)idx * PF4) : zero;
    }

    const size_t R = (size_t)(BSF / 4);      // region stride in float4
    float4* hi1out = out + R + ((size_t)b * PS) * PF4 + f4;   // region 1, row n

#pragma unroll
    for (int j = 0; j < 4; ++j) {
        float4 al = zero, ah = zero;
#pragma unroll
        for (int k = 0; k < 8; ++k) {
            const float4 w = v[2 * j + k];
            const float h0 = c_H0[k], h1 = c_H1[k];
            al.x = fmaf(h0, w.x, al.x); al.y = fmaf(h0, w.y, al.y);
            al.z = fmaf(h0, w.z, al.z); al.w = fmaf(h0, w.w, al.w);
            ah.x = fmaf(h1, w.x, ah.x); ah.y = fmaf(h1, w.y, ah.y);
            ah.z = fmaf(h1, w.z, ah.z); ah.w = fmaf(h1, w.w, ah.w);
        }
        hi1out[(size_t)(n0 + j) * PF4] = ah;          // details[0] == hi1, always kept
        s_lo[(tq << 2) + j][f4] = al;
    }
    __syncthreads();

    // Transpose tile out: (B,F4,T1), coalesced along n
    const int no   = threadIdx.x & 63;
    const int f4o0 = threadIdx.x >> 6;       // 0..3
#pragma unroll
    for (int r = 0; r < 4; ++r) {
        const int f4o = f4o0 + (r << 2);
        g_lo1t[((size_t)b * PF4 + f4o) * T1 + nblk + no] = s_lo[no][f4o];
    }
}

// ---------------------------------------------------------------------------
// Kernel B: fused levels 2..5, one block per (b,f4) column, cascade in smem.
// Buffers hold signal with 3 left + 3 right zero guard cells:
//   buf[3+j] = signal[j];  read signal[2n-3+k] == buf[2n+k].
// ---------------------------------------------------------------------------
#define CASC_SMEM ((2054 + 1030) * (int)sizeof(float4))

__global__ void __launch_bounds__(256) cascade_kernel() {
    extern __shared__ float4 sm[];
    float4* A  = sm;           // 2054: lo1 (T=2048), later lo3 (T=512)
    float4* Bb = sm + 2054;    // 1030: lo2 (T=1024), later lo4 (T=256)

    const int col = blockIdx.x;            // b*16 + f4
    const int tid = threadIdx.x;           // 256 threads

    if (tid < 3) {
        A[tid]  = make_float4(0.f, 0.f, 0.f, 0.f);
        A[3 + T1 + tid] = make_float4(0.f, 0.f, 0.f, 0.f);
        Bb[tid] = make_float4(0.f, 0.f, 0.f, 0.f);
        Bb[3 + T2 + tid] = make_float4(0.f, 0.f, 0.f, 0.f);
    }
    const float4* src = g_lo1t + (size_t)col * T1;
#pragma unroll
    for (int i = tid; i < T1; i += 256) A[3 + i] = __ldg(src + i);
    __syncthreads();

#define AFB_TAPS(BUF, N, LO, HI)                                               \
    {                                                                          \
        LO = make_float4(0.f, 0.f, 0.f, 0.f);                                  \
        HI = make_float4(0.f, 0.f, 0.f, 0.f);                                  \
        _Pragma("unroll")                                                      \
        for (int k = 0; k < 8; ++k) {                                          \
            const float4 v = BUF[2 * (N) + k];                                 \
            const float h0 = c_H0[k], h1 = c_H1[k];                            \
            LO.x = fmaf(h0, v.x, LO.x); LO.y = fmaf(h0, v.y, LO.y);            \
            LO.z = fmaf(h0, v.z, LO.z); LO.w = fmaf(h0, v.w, LO.w);            \
            HI.x = fmaf(h1, v.x, HI.x); HI.y = fmaf(h1, v.y, HI.y);            \
            HI.z = fmaf(h1, v.z, HI.z); HI.w = fmaf(h1, v.w, HI.w);            \
        }                                                                      \
    }

    // level 2: A(T1) -> Bb(T2) + globals
    float4* lo2g = g_lo2t + (size_t)col * T2;
    float4* hi2g = g_hi2t + (size_t)col * T2;
#pragma unroll
    for (int n = tid; n < T2; n += 256) {
        float4 lo, hi; AFB_TAPS(A, n, lo, hi);
        Bb[3 + n] = lo; lo2g[n] = lo; hi2g[n] = hi;
    }
    __syncthreads();

    // level 3: Bb(T2) -> A(T3) + globals
    if (tid < 3) { A[tid] = make_float4(0.f,0.f,0.f,0.f); A[3 + T3 + tid] = make_float4(0.f,0.f,0.f,0.f); }
    __syncthreads();
    float4* lo3g = g_lo3t + (size_t)col * T3;
    float4* hi3g = g_hi3t + (size_t)col * T3;
#pragma unroll
    for (int n = tid; n < T3; n += 256) {
        float4 lo, hi; AFB_TAPS(Bb, n, lo, hi);
        A[3 + n] = lo; lo3g[n] = lo; hi3g[n] = hi;
    }
    __syncthreads();

    // level 4: A(T3) -> Bb(T4) + globals
    if (tid < 3) { Bb[tid] = make_float4(0.f,0.f,0.f,0.f); Bb[3 + T4 + tid] = make_float4(0.f,0.f,0.f,0.f); }
    __syncthreads();
    float4* lo4g = g_lo4t + (size_t)col * T4;
    float4* hi4g = g_hi4t + (size_t)col * T4;
    if (tid < T4) {
        float4 lo, hi; AFB_TAPS(A, tid, lo, hi);
        Bb[3 + tid] = lo; lo4g[tid] = lo; hi4g[tid] = hi;
    }
    __syncthreads();

    // level 5: Bb(T4) -> globals only
    float4* lo5g = g_lo5t + (size_t)col * T5;
    float4* hi5g = g_hi5t + (size_t)col * T5;
    if (tid < T5) {
        float4 lo, hi; AFB_TAPS(Bb, tid, lo, hi);
        lo5g[tid] = lo; hi5g[tid] = hi;
    }
#undef AFB_TAPS
}

// ---------------------------------------------------------------------------
// Kernel C: assemble.
// Regions: [0]=approx [1..5]=details [6]=high_freq [7]=low_freq
// Region 1 (detail 1 == hi1) was already written by level1 for s < T1; here we
// read it back for the high_freq sum, and zero-fill only its s >= T1 tail.
// ---------------------------------------------------------------------------
__device__ __forceinline__ float approx_fetch(int L, int bf, int s, int c) {
    switch (L) {
        case 2: return (s < T2) ? __ldg((const float*)(g_lo2t + (size_t)bf * T2 + s) + c) : 0.f;
        case 3: return (s < T3) ? __ldg((const float*)(g_lo3t + (size_t)bf * T3 + s) + c) : 0.f;
        case 4: return (s < T4) ? __ldg((const float*)(g_lo4t + (size_t)bf * T4 + s) + c) : 0.f;
        default: return (s < T5) ? __ldg((const float*)(g_lo5t + (size_t)bf * T5 + s) + c) : 0.f;
    }
}

__global__ void __launch_bounds__(256) assemble_kernel(const float* __restrict__ scores,
                                                       float4* __restrict__ out) {
    const int f4 = threadIdx.x & 15;
    const int s  = (blockIdx.x << 4) + (threadIdx.x >> 4);
    const int b  = blockIdx.y;
    const int bf = b * PF4 + f4;

    const float4 sc = __ldg((const float4*)scores + f4);
    const int L0 = min(5, max(2, 2 + __float2int_rn(sc.x * 3.0f)));
    const int L1 = min(5, max(2, 2 + __float2int_rn(sc.y * 3.0f)));
    const int L2 = min(5, max(2, 2 + __float2int_rn(sc.z * 3.0f)));
    const int L3 = min(5, max(2, 2 + __float2int_rn(sc.w * 3.0f)));

    const float4 zero = make_float4(0.f, 0.f, 0.f, 0.f);
    const size_t idx = ((size_t)b * PS + s) * PF4 + f4;
    const size_t R = (size_t)(BSF / 4);   // region stride in float4

    // detail 1: written by level1 into out region 1; read back (warp-uniform branch)
    float4 d0;
    if (s < T1) {
        d0 = __ldg(out + R + idx);
    } else {
        d0 = zero;
        __stcs(out + R + idx, zero);      // zero tail of region 1
    }

    float4 d1 = (s < T2) ? __ldg(g_hi2t + (size_t)bf * T2 + s) : zero;
    float4 d2 = (s < T3) ? __ldg(g_hi3t + (size_t)bf * T3 + s) : zero;
    float4 d3 = (s < T4) ? __ldg(g_hi4t + (size_t)bf * T4 + s) : zero;
    float4 d4 = (s < T5) ? __ldg(g_hi5t + (size_t)bf * T5 + s) : zero;

    // detail i kept iff i < level (i=0,1 always kept since level >= 2)
    d2.x = (L0 > 2) ? d2.x : 0.f;  d2.y = (L1 > 2) ? d2.y : 0.f;
    d2.z = (L2 > 2) ? d2.z : 0.f;  d2.w = (L3 > 2) ? d2.w : 0.f;
    d3.x = (L0 > 3) ? d3.x : 0.f;  d3.y = (L1 > 3) ? d3.y : 0.f;
    d3.z = (L2 > 3) ? d3.z : 0.f;  d3.w = (L3 > 3) ? d3.w : 0.f;
    d4.x = (L0 > 4) ? d4.x : 0.f;  d4.y = (L1 > 4) ? d4.y : 0.f;
    d4.z = (L2 > 4) ? d4.z : 0.f;  d4.w = (L3 > 4) ? d4.w : 0.f;

    float4 a;
    a.x = approx_fetch(L0, bf, s, 0);
    a.y = approx_fetch(L1, bf, s, 1);
    a.z = approx_fetch(L2, bf, s, 2);
    a.w = approx_fetch(L3, bf, s, 3);

    float4 hf;
    hf.x = d0.x + d1.x + d2.x + d3.x + d4.x;
    hf.y = d0.y + d1.y + d2.y + d3.y + d4.y;
    hf.z = d0.z + d1.z + d2.z + d3.z + d4.z;
    hf.w = d0.w + d1.w + d2.w + d3.w + d4.w;

    __stcs(out + idx,         a);
    __stcs(out + 2 * R + idx, d1);
    __stcs(out + 3 * R + idx, d2);
    __stcs(out + 4 * R + idx, d3);
    __stcs(out + 5 * R + idx, d4);
    __stcs(out + 6 * R + idx, hf);
    __stcs(out + 7 * R + idx, a);   // low_freq == approx
}

extern "C" void kernel_launch(void* const* d_in, const int* in_sizes, int n_in,
                              void* d_out, int out_size) {
    const float4* x      = (const float4*)d_in[0];   // (32, 4096, 64) f32
    const float*  scores = (const float*)d_in[1];    // (64,) f32
    float4* out = (float4*)d_out;

    cudaFuncSetAttribute(cascade_kernel,
                         cudaFuncAttributeMaxDynamicSharedMemorySize, CASC_SMEM);

    const dim3 blk(256);
    level1_kernel <<<dim3(T1 / 64, PB), blk>>>(x, out);
    cascade_kernel<<<dim3(PB * PF4), blk, CASC_SMEM>>>();
    assemble_kernel<<<dim3(PS / 16, PB), blk>>>(scores, out);
}

// round 11
// speedup vs baseline: 1.1623x; 1.0172x over previous
#include <cuda_runtime.h>

// Problem constants
#define PB 32
#define PS 4096
#define PF 64
#define PF4 16                         // F in float4 units
#define T1 2048
#define T2 1024
#define T3 512
#define T4 256
#define T5 128
#define BSF (32LL * 4096LL * 64LL)     // elements per output region

// Analysis filters: H = reversed db4 dec filters (cross-correlation form)
__constant__ float c_H0[8] = {
     0.23037781330885523f,  0.7148465705525415f,   0.6308807679295904f,
    -0.02798376941698385f, -0.18703481171888114f,  0.030841381835986965f,
     0.032883011666982945f, -0.010597401784997278f };
__constant__ float c_H1[8] = {
    -0.010597401784997278f, -0.032883011666982945f, 0.030841381835986965f,
     0.18703481171888114f,  -0.02798376941698385f, -0.6308807679295904f,
     0.7148465705525415f,   -0.23037781330885523f };

// Static scratch, column-major (B,F4,T): element (b,f4,t) is a float4 of 4
// adjacent features; contiguous in t.
__device__ float4 g_lo1t[PB * PF4 * T1];   // (B,F4,T1) lowpass after level 1
__device__ float4 g_hi2t[PB * PF4 * T2];   // detail 2 (always kept)
__device__ float4 g_hi3t[PB * PF4 * T3];   // detail 3, PRE-MASKED (L>2)
__device__ float4 g_hi4t[PB * PF4 * T4];   // detail 4, PRE-MASKED (L>3)
__device__ float4 g_hi5t[PB * PF4 * T5];   // detail 5, PRE-MASKED (L>4)
__device__ float4 g_apxt[PB * PF4 * T2];   // approx, PRE-SELECTED per feature level

// ---------------------------------------------------------------------------
// Kernel A: level 1, smem-staged.
// Block = 32 outputs x 16 f4 for one b. Stage 70 input rows once (coalesced),
// compute taps from smem (ptxas CSEs overlapping taps), write hi1 directly to
// out region 1 and lo1 to (B,F4,T1) scratch via an in-place smem transpose.
// ---------------------------------------------------------------------------
#define L1_OUT  32
#define L1_ROWS (2 * L1_OUT + 6)    // 70

__global__ void __launch_bounds__(256) level1_kernel(const float4* __restrict__ x,
                                                     float4* __restrict__ out) {
    __shared__ float4 s[L1_ROWS * PF4];   // 1120 float4; reused for transpose (needs 544)

    const int tid  = threadIdx.x;
    const int b    = blockIdx.y;
    const int nblk = blockIdx.x * L1_OUT;
    const int base = 2 * nblk - 3;
    const float4 zero = make_float4(0.f, 0.f, 0.f, 0.f);

    // Stage input rows base .. base+69 (zero outside [0,PS))
    const float4* xb = x + (size_t)b * PS * PF4;
#pragma unroll
    for (int i = tid; i < L1_ROWS * PF4; i += 256) {
        const int r = i >> 4, f = i & 15;
        const int g = base + r;
        s[i] = (g >= 0 && g < PS) ? __ldg(xb + (size_t)g * PF4 + f) : zero;
    }
    __syncthreads();

    const int f4 = tid & 15;
    const int tq = tid >> 4;          // 0..15, 2 outputs each
    const int j0 = tq << 1;           // local output index (0,2,..,30)

    const size_t R = (size_t)(BSF / 4);
    float4 al0, al1;
    {
        float4* hi1out = out + R + ((size_t)b * PS + nblk + j0) * PF4 + f4;
#pragma unroll
        for (int j = 0; j < 2; ++j) {
            float4 a = zero, h = zero;
#pragma unroll
            for (int k = 0; k < 8; ++k) {
                const float4 w = s[(2 * (j0 + j) + k) * PF4 + f4];
                const float h0 = c_H0[k], h1 = c_H1[k];
                a.x = fmaf(h0, w.x, a.x); a.y = fmaf(h0, w.y, a.y);
                a.z = fmaf(h0, w.z, a.z); a.w = fmaf(h0, w.w, a.w);
                h.x = fmaf(h1, w.x, h.x); h.y = fmaf(h1, w.y, h.y);
                h.z = fmaf(h1, w.z, h.z); h.w = fmaf(h1, w.w, h.w);
            }
            hi1out[(size_t)j * PF4] = h;          // details[0] == hi1, always kept
            if (j == 0) al0 = a; else al1 = a;
        }
    }
    __syncthreads();                  // staging reads complete

    // In-place transpose of lo through smem: s[n*17 + f4]
    s[j0 * 17 + f4]       = al0;
    s[(j0 + 1) * 17 + f4] = al1;
    __syncthreads();

    // Write lo1t coalesced along n: 32 n x 16 f4, 2 per thread
    const int no   = tid & 31;
    const int f4o0 = tid >> 5;        // 0..7
#pragma unroll
    for (int r2 = 0; r2 < 2; ++r2) {
        const int f4o = f4o0 + (r2 << 3);
        g_lo1t[((size_t)b * PF4 + f4o) * T1 + nblk + no] = s[no * 17 + f4o];
    }
}

// ---------------------------------------------------------------------------
// Kernel B: fused levels 2..5 + per-feature masking + approx selection.
// One block per (b,f4) column; lo cascade entirely in smem (separate buffers,
// each with 3+3 zero guard cells: buf[3+j] = sig[j], taps read buf[2n+k]).
// ---------------------------------------------------------------------------
#define SM_A  0                        // lo1: 2048 + 6
#define SM_B2 2054                     // lo2: 1024 + 6
#define SM_B3 (SM_B2 + 1030)           // lo3: 512 + 6
#define SM_B4 (SM_B3 + 518)            // lo4: 256 + 6
#define SM_B5 (SM_B4 + 262)            // lo5: 128 (no guards needed)
#define CASC_SMEM ((SM_B5 + 128) * (int)sizeof(float4))

__global__ void __launch_bounds__(256) cascade_kernel(const float* __restrict__ scores) {
    extern __shared__ float4 sm[];
    float4* A  = sm + SM_A;
    float4* B2 = sm + SM_B2;
    float4* B3 = sm + SM_B3;
    float4* B4 = sm + SM_B4;
    float4* B5 = sm + SM_B5;

    const int col = blockIdx.x;            // b*16 + f4
    const int f4  = col & 15;
    const int tid = threadIdx.x;           // 256 threads
    const float4 zero = make_float4(0.f, 0.f, 0.f, 0.f);

    // per-feature decomposition levels for this column's 4 features
    const float4 sc = __ldg((const float4*)scores + f4);
    const int L0 = min(5, max(2, 2 + __float2int_rn(sc.x * 3.0f)));
    const int L1v = min(5, max(2, 2 + __float2int_rn(sc.y * 3.0f)));
    const int L2v = min(5, max(2, 2 + __float2int_rn(sc.z * 3.0f)));
    const int L3v = min(5, max(2, 2 + __float2int_rn(sc.w * 3.0f)));

    if (tid < 3) {
        A[tid]  = zero; A[3 + T1 + tid]  = zero;
        B2[tid] = zero; B2[3 + T2 + tid] = zero;
        B3[tid] = zero; B3[3 + T3 + tid] = zero;
        B4[tid] = zero; B4[3 + T4 + tid] = zero;
    }
    const float4* src = g_lo1t + (size_t)col * T1;
#pragma unroll
    for (int i = tid; i < T1; i += 256) A[3 + i] = __ldg(src + i);
    __syncthreads();

#define AFB_TAPS(BUF, N, LO, HI)                                               \
    {                                                                          \
        LO = make_float4(0.f, 0.f, 0.f, 0.f);                                  \
        HI = make_float4(0.f, 0.f, 0.f, 0.f);                                  \
        _Pragma("unroll")                                                      \
        for (int k = 0; k < 8; ++k) {                                          \
            const float4 v = BUF[2 * (N) + k];                                 \
            const float h0 = c_H0[k], h1 = c_H1[k];                            \
            LO.x = fmaf(h0, v.x, LO.x); LO.y = fmaf(h0, v.y, LO.y);            \
            LO.z = fmaf(h0, v.z, LO.z); LO.w = fmaf(h0, v.w, LO.w);            \
            HI.x = fmaf(h1, v.x, HI.x); HI.y = fmaf(h1, v.y, HI.y);            \
            HI.z = fmaf(h1, v.z, HI.z); HI.w = fmaf(h1, v.w, HI.w);            \
        }                                                                      \
    }

    // level 2: A(T1) -> B2 + hi2 (always kept, no mask)
    float4* hi2g = g_hi2t + (size_t)col * T2;
#pragma unroll
    for (int n = tid; n < T2; n += 256) {
        float4 lo, hi; AFB_TAPS(A, n, lo, hi);
        B2[3 + n] = lo; hi2g[n] = hi;
    }
    __syncthreads();

    // level 3: B2(T2) -> B3 + hi3 masked (kept iff L > 2)
    float4* hi3g = g_hi3t + (size_t)col * T3;
#pragma unroll
    for (int n = tid; n < T3; n += 256) {
        float4 lo, hi; AFB_TAPS(B2, n, lo, hi);
        B3[3 + n] = lo;
        hi.x = (L0  > 2) ? hi.x : 0.f;  hi.y = (L1v > 2) ? hi.y : 0.f;
        hi.z = (L2v > 2) ? hi.z : 0.f;  hi.w = (L3v > 2) ? hi.w : 0.f;
        hi3g[n] = hi;
    }
    __syncthreads();

    // level 4: B3(T3) -> B4 + hi4 masked (kept iff L > 3)
    float4* hi4g = g_hi4t + (size_t)col * T4;
    if (tid < T4) {
        float4 lo, hi; AFB_TAPS(B3, tid, lo, hi);
        B4[3 + tid] = lo;
        hi.x = (L0  > 3) ? hi.x : 0.f;  hi.y = (L1v > 3) ? hi.y : 0.f;
        hi.z = (L2v > 3) ? hi.z : 0.f;  hi.w = (L3v > 3) ? hi.w : 0.f;
        hi4g[tid] = hi;
    }
    __syncthreads();

    // level 5: B4(T4) -> B5 + hi5 masked (kept iff L > 4)
    float4* hi5g = g_hi5t + (size_t)col * T5;
    if (tid < T5) {
        float4 lo, hi; AFB_TAPS(B4, tid, lo, hi);
        B5[tid] = lo;
        hi.x = (L0  > 4) ? hi.x : 0.f;  hi.y = (L1v > 4) ? hi.y : 0.f;
        hi.z = (L2v > 4) ? hi.z : 0.f;  hi.w = (L3v > 4) ? hi.w : 0.f;
        hi5g[tid] = hi;
    }
    __syncthreads();

    // approx selection: apx[t].c = lo{L_c}[t] (zero beyond that level's length)
    float4* apxg = g_apxt + (size_t)col * T2;
#pragma unroll
    for (int t = tid; t < T2; t += 256) {
        const float4 v2 = B2[3 + t];
        const float4 v3 = (t < T3) ? B3[3 + t] : zero;
        const float4 v4 = (t < T4) ? B4[3 + t] : zero;
        const float4 v5 = (t < T5) ? B5[t]     : zero;
        float4 a;
        a.x = (L0  == 2) ? v2.x : (L0  == 3) ? v3.x : (L0  == 4) ? v4.x : v5.x;
        a.y = (L1v == 2) ? v2.y : (L1v == 3) ? v3.y : (L1v == 4) ? v4.y : v5.y;
        a.z = (L2v == 2) ? v2.z : (L2v == 3) ? v3.z : (L2v == 4) ? v4.z : v5.z;
        a.w = (L3v == 2) ? v2.w : (L3v == 3) ? v3.w : (L3v == 4) ? v4.w : v5.w;
        apxg[t] = a;
    }
#undef AFB_TAPS
}

// ---------------------------------------------------------------------------
// Kernel C: assemble — pure streaming, no selection logic left.
// Regions: [0]=approx [1..5]=details [6]=high_freq [7]=low_freq
// Region 1 (detail 1 == hi1) already written by level1 for s < T1; read back
// for high_freq, zero-fill its s >= T1 tail.
// ---------------------------------------------------------------------------
__global__ void __launch_bounds__(256) assemble_kernel(float4* __restrict__ out) {
    const int f4 = threadIdx.x & 15;
    const int s  = (blockIdx.x << 4) + (threadIdx.x >> 4);
    const int b  = blockIdx.y;
    const int bf = b * PF4 + f4;

    const float4 zero = make_float4(0.f, 0.f, 0.f, 0.f);
    const size_t idx = ((size_t)b * PS + s) * PF4 + f4;
    const size_t R = (size_t)(BSF / 4);   // region stride in float4

    // detail 1: written by level1 into out region 1 (warp-uniform branch)
    float4 d0;
    if (s < T1) {
        d0 = __ldg(out + R + idx);
    } else {
        d0 = zero;
        __stcs(out + R + idx, zero);      // zero tail of region 1
    }

    const float4 a  = (s < T2) ? __ldg(g_apxt + (size_t)bf * T2 + s) : zero;
    const float4 d1 = (s < T2) ? __ldg(g_hi2t + (size_t)bf * T2 + s) : zero;
    const float4 d2 = (s < T3) ? __ldg(g_hi3t + (size_t)bf * T3 + s) : zero;  // pre-masked
    const float4 d3 = (s < T4) ? __ldg(g_hi4t + (size_t)bf * T4 + s) : zero;  // pre-masked
    const float4 d4 = (s < T5) ? __ldg(g_hi5t + (size_t)bf * T5 + s) : zero;  // pre-masked

    float4 hf;
    hf.x = d0.x + d1.x + d2.x + d3.x + d4.x;
    hf.y = d0.y + d1.y + d2.y + d3.y + d4.y;
    hf.z = d0.z + d1.z + d2.z + d3.z + d4.z;
    hf.w = d0.w + d1.w + d2.w + d3.w + d4.w;

    __stcs(out + idx,         a);
    __stcs(out + 2 * R + idx, d1);
    __stcs(out + 3 * R + idx, d2);
    __stcs(out + 4 * R + idx, d3);
    __stcs(out + 5 * R + idx, d4);
    __stcs(out + 6 * R + idx, hf);
    __stcs(out + 7 * R + idx, a);   // low_freq == approx
}

extern "C" void kernel_launch(void* const* d_in, const int* in_sizes, int n_in,
                              void* d_out, int out_size) {
    const float4* x      = (const float4*)d_in[0];   // (32, 4096, 64) f32
    const float*  scores = (const float*)d_in[1];    // (64,) f32
    float4* out = (float4*)d_out;

    cudaFuncSetAttribute(cascade_kernel,
                         cudaFuncAttributeMaxDynamicSharedMemorySize, CASC_SMEM);

    const dim3 blk(256);
    level1_kernel <<<dim3(T1 / L1_OUT, PB), blk>>>(x, out);
    cascade_kernel<<<dim3(PB * PF4), blk, CASC_SMEM>>>(scores);
    assemble_kernel<<<dim3(PS / 16, PB), blk>>>(out);
}